// round 6
// baseline (speedup 1.0000x reference)
#include <cuda_runtime.h>
#include <cuda_bf16.h>

// SSM kernel: out[l, i] = exp(l * a_i) * (B_i * C_i) + D,  a_i = A[i][i]
// L = 262144, n = 256. Output 256 MiB fp32 -> pure streaming-store bound.
//
// Converged at the HBM write roofline (~6.3 TB/s):
//   16 w/SM -> 3.47 TB/s (starved) | 24-48 w/SM -> 6.30-6.31 TB/s (plateau)
//   64 w/SM -> 6.14 TB/s (contention)
// R6: lock in the plateau config (592 = 148*4 blocks x 256 thr, 64-row
//     grid-stride chunks) and drop all index math to 32-bit (max index
//     2^24 float4) to cut regs 48 -> ~30 and per-iter IMADs.

#define N_COLS 256
#define CGROUPS 64              // 64 float4 per row
#define CHUNK_ROWS 64           // rows per chunk per block per grid-stride step
#define TY 4                    // row sub-chunks per block (256 threads / 64)
#define RPT 16                  // rows per thread per chunk (CHUNK_ROWS/TY)
#define GRID_BLOCKS 592         // 148 SMs * 4 CTAs, balanced

__global__ __launch_bounds__(256, 4)
void ssm_kernel(const float* __restrict__ A,
                const float* __restrict__ B,
                const float* __restrict__ C,
                const float* __restrict__ D,
                float4* __restrict__ out,
                int nchunks)
{
    const int tx = threadIdx.x & 63;        // column group: cols 4*tx .. 4*tx+3
    const int ty = threadIdx.x >> 6;        // row sub-chunk within chunk (0..3)

    const float d = D[0];
    const float LOG2E = 1.4426950408889634f;

    // rows skipped hopping from the end of this thread's rows in one chunk
    // to the start of its rows in its next grid-stride chunk
    const float hop_rows = (float)(GRID_BLOCKS * CHUNK_ROWS - RPT);

    const int first_row = blockIdx.x * CHUNK_ROWS + ty * RPT;  // < 2^19

    float r[4], pm[4], bc[4], jmp[4];
#pragma unroll
    for (int k = 0; k < 4; k++) {
        const int j = tx * 4 + k;
        const float a = A[j * N_COLS + j];            // diag (strictly negative)
        r[k]   = __expf(a);                           // per-row decay ratio
        jmp[k] = exp2f(hop_rows * a * LOG2E);         // chunk-hop factor
        pm[k]  = exp2f((float)first_row * a * LOG2E); // exact anchor
        bc[k]  = B[j] * C[j];
    }

    // 32-bit addressing: total float4 entries = L*64 = 2^24, chunk stride in
    // float4 units = CHUNK_ROWS*CGROUPS = 4096; all fits comfortably in int.
    int base = first_row * CGROUPS + tx;
    const int chunk_stride = GRID_BLOCKS * CHUNK_ROWS * CGROUPS
                           - RPT * CGROUPS;           // hop in float4 units
    const int total = nchunks * CHUNK_ROWS * CGROUPS; // 2^24

    while (base < total) {
        int p = base;
#pragma unroll
        for (int l = 0; l < RPT; l++) {
            float4 v;
            v.x = fmaf(pm[0], bc[0], d);
            v.y = fmaf(pm[1], bc[1], d);
            v.z = fmaf(pm[2], bc[2], d);
            v.w = fmaf(pm[3], bc[3], d);
            __stcs(&out[p], v);                       // streaming store
            p += CGROUPS;
            pm[0] *= r[0];
            pm[1] *= r[1];
            pm[2] *= r[2];
            pm[3] *= r[3];
        }
        // hop to this thread's rows in the next grid-stride chunk
        pm[0] *= jmp[0];
        pm[1] *= jmp[1];
        pm[2] *= jmp[2];
        pm[3] *= jmp[3];
        base += RPT * CGROUPS + chunk_stride;
    }
}

extern "C" void kernel_launch(void* const* d_in, const int* in_sizes, int n_in,
                              void* d_out, int out_size)
{
    // Inputs per reference order: (optional scalar L), A (n*n), B (n), C (n), D (1)
    int base = 0;
    if (n_in >= 5) base = n_in - 4;
    const float* A = (const float*)d_in[base + 0];
    const float* B = (const float*)d_in[base + 1];
    const float* C = (const float*)d_in[base + 2];
    const float* D = (const float*)d_in[base + 3];

    const int L = out_size / N_COLS;            // 262144
    const int nchunks = L / CHUNK_ROWS;         // 4096

    ssm_kernel<<<GRID_BLOCKS, 256>>>(A, B, C, D, (float4*)d_out, nchunks);
}